// round 12
// baseline (speedup 1.0000x reference)
#include <cuda_runtime.h>
#include <cuda_bf16.h>
#include <cstdint>

#define NODES      10000
#define DIM        256
#define NTOT       262144          // 4096 * 64
#define CAP        128             // fixed per-node bucket capacity (mean E=13.1)
#define XC         32              // cached-rows bound (+5 sigma of E distribution)

// ---------------- device scratch ----------------
// g_cursor: zero at module load; attn_kernel re-zeroes after use -> invariant
// "all cursors are 0 at kernel_launch entry" holds across graph replays.
__device__ float g_q[NODES * DIM];
__device__ float g_update[NODES * DIM];
__device__ int   g_cursor[NODES];
__device__ int   g_entries[NODES * CAP];

__device__ __forceinline__ void mma_tf32(float* c, const uint32_t* a, const uint32_t* b) {
    asm volatile(
        "mma.sync.aligned.m16n8k8.row.col.f32.tf32.tf32.f32 "
        "{%0,%1,%2,%3}, {%4,%5,%6,%7}, {%8,%9}, {%0,%1,%2,%3};"
        : "+f"(c[0]), "+f"(c[1]), "+f"(c[2]), "+f"(c[3])
        : "r"(a[0]), "r"(a[1]), "r"(a[2]), "r"(a[3]), "r"(b[0]), "r"(b[1]));
}

__device__ __forceinline__ void cp_async16p(void* dst, const void* src, bool pred) {
    uint32_t d = (uint32_t)__cvta_generic_to_shared(dst);
    int sz = pred ? 16 : 0;
    asm volatile("cp.async.cg.shared.global [%0], [%1], 16, %2;\n"
                 :: "r"(d), "l"(src), "r"(sz));
}
__device__ __forceinline__ void cp_async16(void* dst, const void* src) {
    uint32_t d = (uint32_t)__cvta_generic_to_shared(dst);
    asm volatile("cp.async.cg.shared.global [%0], [%1], 16;\n"
                 :: "r"(d), "l"(src));
}
#define CP_COMMIT() asm volatile("cp.async.commit_group;\n" ::)
#define CP_WAIT(n)  asm volatile("cp.async.wait_group %0;\n" :: "n"(n))

__device__ __forceinline__ bool read_mask(const void* m, int i, int mode) {
    if (mode == 1) return ((const uint8_t*)m)[i] != 0;
    if (mode == 2) return ((const float*)m)[i] != 0.0f;
    return ((const int*)m)[i] != 0;
}

// ---------------- GEMM geometry ----------------
#define GBM 128
#define GBN 64
#define QGX (256 / GBN)                          // 4
#define QGY ((NODES + GBM - 1) / GBM)            // 79
#define QBLOCKS (QGX * QGY)                      // 316
#define FILL_BLOCKS (NTOT / 4 / 256)             // 256
#define CSTR 65                                  // staged-C smem stride (floats)

union SmemU {
    struct { float4 A[2][1024]; float4 B[2][512]; } p;   // 48 KB
    float C[GBM * CSTR];                                  // 33.3 KB
    int   probe[2];
};

__device__ __forceinline__ int a_idx(int r, int k) {   // float index, A stage 128x32
    int ch = k >> 2;
    return r * 32 + ((ch ^ (r & 7)) << 2) + (k & 3);
}
__device__ __forceinline__ int b_idx(int k, int n) {   // float index, B stage 32x64
    int ch = n >> 2;
    return k * 64 + ((ch ^ ((k & 3) << 1)) << 2) + (n & 3);
}

__device__ __forceinline__ void load_a_tile(float4* sa, const float* __restrict__ Asrc,
                                            int row0, int k0, int M) {
    int tid = threadIdx.x;
    #pragma unroll
    for (int t = 0; t < 4; t++) {
        int cl = tid + t * 256;            // 0..1023
        int r = cl >> 3, ch = cl & 7;
        int gr = row0 + r;
        const float* src = Asrc + (size_t)gr * 256 + k0 + ch * 4;
        cp_async16p(&sa[r * 8 + (ch ^ (r & 7))], src, gr < M);
    }
}
__device__ __forceinline__ void load_b_tile(float4* sb, const float* __restrict__ Bsrc,
                                            int col0, int k0) {
    int tid = threadIdx.x;
    #pragma unroll
    for (int t = 0; t < 2; t++) {
        int cl = tid + t * 256;            // 0..511
        int k = cl >> 4, ch = cl & 15;
        const float* src = Bsrc + (size_t)(k0 + k) * 256 + col0 + ch * 4;
        cp_async16(&sb[k * 16 + (ch ^ ((k & 3) << 1))], src);
    }
}

__device__ __forceinline__ void mma_stage(const float* __restrict__ As,
                                          const float* __restrict__ Bs,
                                          int wm, int wn, int tig, int grp,
                                          float c[2][4][4]) {
    #pragma unroll
    for (int g = 0; g < 4; g++) {
        int k1 = g * 8 + tig;
        uint32_t a[2][4], b[4][2];
        #pragma unroll
        for (int mt = 0; mt < 2; mt++) {
            int r = wm * 32 + mt * 16 + grp;
            a[mt][0] = __float_as_uint(As[a_idx(r,     k1)]);
            a[mt][1] = __float_as_uint(As[a_idx(r + 8, k1)]);
            a[mt][2] = __float_as_uint(As[a_idx(r,     k1 + 4)]);
            a[mt][3] = __float_as_uint(As[a_idx(r + 8, k1 + 4)]);
        }
        #pragma unroll
        for (int nt = 0; nt < 4; nt++) {
            int cc = wn * 32 + nt * 8 + grp;
            b[nt][0] = __float_as_uint(Bs[b_idx(k1,     cc)]);
            b[nt][1] = __float_as_uint(Bs[b_idx(k1 + 4, cc)]);
        }
        #pragma unroll
        for (int mt = 0; mt < 2; mt++)
            #pragma unroll
            for (int nt = 0; nt < 4; nt++)
                mma_tf32(c[mt][nt], a[mt], b[nt]);
    }
}

// ---- stage accumulators into smem C (stride-65 avoids bank conflicts) ----
__device__ __forceinline__ void stage_c(SmemU& sm, float c[2][4][4],
                                        int wm, int wn, int tig, int grp) {
    #pragma unroll
    for (int mt = 0; mt < 2; mt++)
        #pragma unroll
        for (int i = 0; i < 2; i++) {
            int r = wm * 32 + mt * 16 + grp + i * 8;
            #pragma unroll
            for (int nt = 0; nt < 4; nt++)
                #pragma unroll
                for (int jj = 0; jj < 2; jj++) {
                    int cc = wn * 32 + nt * 8 + tig * 2 + jj;
                    sm.C[r * CSTR + cc] = c[mt][nt][i * 2 + jj];
                }
        }
}

// ---- q-GEMM body: cp.async double-buffered, K=256, coalesced staged store ----
__device__ void gemm_q_body(SmemU& sm, const float* __restrict__ A,
                            const float* __restrict__ B, int M, int bx, int by) {
    int tid = threadIdx.x;
    int wid = tid >> 5, lane = tid & 31;
    int tig = lane & 3, grp = lane >> 2;
    int wm = wid & 3, wn = wid >> 2;
    int row0 = by * GBM, col0 = bx * GBN;
    float c[2][4][4] = {};

    load_a_tile(sm.p.A[0], A, row0, 0, M);
    load_b_tile(sm.p.B[0], B, col0, 0);
    CP_COMMIT();
    const int T = 8;
    for (int t = 0; t < T; t++) {
        int s = t & 1;
        if (t + 1 < T) {
            load_a_tile(sm.p.A[s ^ 1], A, row0, (t + 1) * 32, M);
            load_b_tile(sm.p.B[s ^ 1], B, col0, (t + 1) * 32);
            CP_COMMIT();
            CP_WAIT(1);
        } else {
            CP_WAIT(0);
        }
        __syncthreads();
        mma_stage((const float*)sm.p.A[s], (const float*)sm.p.B[s], wm, wn, tig, grp, c);
        __syncthreads();
    }

    stage_c(sm, c, wm, wn, tig, grp);
    __syncthreads();
    #pragma unroll
    for (int pass = 0; pass < 8; pass++) {
        int r = pass * 16 + (tid >> 4);
        int cq = (tid & 15) * 4;
        int gr = row0 + r;
        if (gr < M) {
            float4 v;
            v.x = sm.C[r * CSTR + cq + 0]; v.y = sm.C[r * CSTR + cq + 1];
            v.z = sm.C[r * CSTR + cq + 2]; v.w = sm.C[r * CSTR + cq + 3];
            *(float4*)&g_q[(size_t)gr * 256 + col0 + cq] = v;
        }
    }
}

// ---- fill body: self-probing mask mode + bump-allocate into buckets ----
__device__ void fill_body(SmemU& sm, const void* __restrict__ mask,
                          const int* __restrict__ idx, int fb) {
    int tid = threadIdx.x;
    if (tid < 2) sm.probe[tid] = 0;
    __syncthreads();
    {
        const uint32_t* mw = (const uint32_t*)mask;
        int l1 = 0, l3 = 0;
        #pragma unroll
        for (int w = 0; w < 8; w++) {
            uint32_t v = mw[tid * 8 + w];
            if (v & 0x0000FF00u) l1++;
            if (v & 0xFF000000u) l3++;
        }
        if (l1) atomicAdd(&sm.probe[0], 1);
        if (l3) atomicAdd(&sm.probe[1], 1);
    }
    __syncthreads();
    int mode = sm.probe[0] ? 1 : (sm.probe[1] ? 2 : 0);

    int base = (fb * 256 + tid) * 4;
    if (base >= NTOT) return;
    int4 id4 = *(const int4*)&idx[base];
    int ids[4] = {id4.x, id4.y, id4.z, id4.w};
    #pragma unroll
    for (int j = 0; j < 4; j++) {
        if (read_mask(mask, base + j, mode)) {
            int n = ids[j];
            int p = atomicAdd(&g_cursor[n], 1);
            if (p < CAP) g_entries[n * CAP + p] = base + j;
        }
    }
}

// ---- fused: q-GEMM blocks + fill blocks in one wave ----
__global__ void fused_gemm_fill_kernel(const float* __restrict__ prev,
                                       const float* __restrict__ Wq,
                                       const void* __restrict__ mask,
                                       const int* __restrict__ idx) {
    __shared__ SmemU sm;
    int b = blockIdx.x;
    if (b < QBLOCKS) gemm_q_body(sm, prev, Wq, NODES, b % QGX, b / QGX);
    else             fill_body(sm, mask, idx, b - QBLOCKS);
}

// ---------------- per-node attention (exact fp32, smem row cache) ----------------
#define NWARPS_ATTN 8
__global__ void attn_kernel(const float* __restrict__ x) {   // [NTOT, 256]
    cudaTriggerProgrammaticLaunchCompletion();

    int node = blockIdx.x;
    int E   = min(g_cursor[node], CAP);
    int tid = threadIdx.x;             // 256 == DIM
    if (E == 0) { g_update[(size_t)node * DIM + tid] = 0.f; return; }
    int lane = tid & 31, wid = tid >> 5;
    const int* gep = g_entries + node * CAP;

    __shared__ float s_x[XC][DIM];     // 32 KB row cache (phase-3 source)
    __shared__ float s_sc[CAP];
    __shared__ int   s_en[CAP];
    if (tid < E) s_en[tid] = gep[tid];
    __syncthreads();
    if (tid == 0) g_cursor[node] = 0;   // reset for next launch (after all reads)

    bool cached = (E <= XC);

    // phase 1: scores, two entries per warp iteration (MLP=4); cache rows in smem
    const float4* qr = (const float4*)(g_q + (size_t)node * DIM);
    float4 b0 = qr[lane * 2], b1 = qr[lane * 2 + 1];
    for (int j = wid * 2; j < E; j += 2 * NWARPS_ATTN) {
        int rA = s_en[j];
        bool has2 = (j + 1 < E);
        int rB = has2 ? s_en[j + 1] : rA;
        const float4* xA = (const float4*)(x + (size_t)rA * DIM);
        const float4* xB = (const float4*)(x + (size_t)rB * DIM);
        float4 a0 = xA[lane * 2], a1 = xA[lane * 2 + 1];
        float4 c0 = xB[lane * 2], c1 = xB[lane * 2 + 1];
        if (cached) {
            float4* dA = (float4*)s_x[j];
            dA[lane * 2] = a0; dA[lane * 2 + 1] = a1;
            if (has2) {
                float4* dB = (float4*)s_x[j + 1];
                dB[lane * 2] = c0; dB[lane * 2 + 1] = c1;
            }
        }
        float sA = a0.x * b0.x + a0.y * b0.y + a0.z * b0.z + a0.w * b0.w
                 + a1.x * b1.x + a1.y * b1.y + a1.z * b1.z + a1.w * b1.w;
        float sB = c0.x * b0.x + c0.y * b0.y + c0.z * b0.z + c0.w * b0.w
                 + c1.x * b1.x + c1.y * b1.y + c1.z * b1.z + c1.w * b1.w;
        #pragma unroll
        for (int off = 16; off; off >>= 1) {
            sA += __shfl_down_sync(0xFFFFFFFFu, sA, off);
            sB += __shfl_down_sync(0xFFFFFFFFu, sB, off);
        }
        if (lane == 0) {
            s_sc[j] = sA * 0.0625f;
            if (has2) s_sc[j + 1] = sB * 0.0625f;
        }
    }
    __syncthreads();

    // phase 2: softmax by warp 0 alone
    if (wid == 0) {
        float mx = -1e30f;
        for (int j = lane; j < E; j += 32) mx = fmaxf(mx, s_sc[j]);
        #pragma unroll
        for (int off = 16; off; off >>= 1) mx = fmaxf(mx, __shfl_xor_sync(0xFFFFFFFFu, mx, off));
        float sm = 0.f;
        for (int j = lane; j < E; j += 32) sm += __expf(s_sc[j] - mx);
        #pragma unroll
        for (int off = 16; off; off >>= 1) sm += __shfl_xor_sync(0xFFFFFFFFu, sm, off);
        float inv = 1.f / fmaxf(sm, 1e-9f);
        for (int j = lane; j < E; j += 32) s_sc[j] = __expf(s_sc[j] - mx) * inv;
    }
    __syncthreads();

    // phase 3: weighted sum, one column per thread
    float acc = 0.f;
    if (cached) {
        int j = 0;
        for (; j + 4 <= E; j += 4) {
            acc += s_sc[j]     * s_x[j][tid]     + s_sc[j + 1] * s_x[j + 1][tid]
                 + s_sc[j + 2] * s_x[j + 2][tid] + s_sc[j + 3] * s_x[j + 3][tid];
        }
        for (; j < E; j++) acc += s_sc[j] * s_x[j][tid];
    } else {
        int j = 0;
        for (; j + 4 <= E; j += 4) {
            int r0 = s_en[j], r1 = s_en[j + 1], r2 = s_en[j + 2], r3 = s_en[j + 3];
            float w0 = s_sc[j], w1 = s_sc[j + 1], w2 = s_sc[j + 2], w3 = s_sc[j + 3];
            acc += w0 * x[(size_t)r0 * DIM + tid] + w1 * x[(size_t)r1 * DIM + tid]
                 + w2 * x[(size_t)r2 * DIM + tid] + w3 * x[(size_t)r3 * DIM + tid];
        }
        for (; j < E; j++) acc += s_sc[j] * x[(size_t)s_en[j] * DIM + tid];
    }
    g_update[(size_t)node * DIM + tid] = acc;
}

// ---------------- gate: PDL-overlapped tf32 GEMM (K=512) ----------------
__global__ void gate_kernel(const float* __restrict__ prev,
                            const float* __restrict__ gateW,
                            const float* __restrict__ gateB,
                            float* __restrict__ out, int M) {
    __shared__ SmemU sm;
    int tid = threadIdx.x;
    int wid = tid >> 5, lane = tid & 31;
    int tig = lane & 3, grp = lane >> 2;
    int wm = wid & 3, wn = wid >> 2;
    int row0 = blockIdx.y * GBM, col0 = blockIdx.x * GBN;
    float c[2][4][4] = {};

    load_a_tile(sm.p.A[0], prev, row0, 0, M);
    load_b_tile(sm.p.B[0], gateW, col0, 0);
    CP_COMMIT();
    const int T = 16;                    // K = 512
    for (int t = 0; t < T; t++) {
        int s = t & 1;
        if (t + 1 < T) {
            int kt = t + 1;
            if (kt == 8) cudaGridDependencySynchronize();   // wait for attn grid
            const float* Asrc = (kt < 8) ? prev : g_update;
            load_a_tile(sm.p.A[s ^ 1], Asrc, row0, (kt * 32) & 255, M);
            load_b_tile(sm.p.B[s ^ 1], gateW, col0, kt * 32);
            CP_COMMIT();
            CP_WAIT(1);
        } else {
            CP_WAIT(0);
        }
        __syncthreads();
        mma_stage((const float*)sm.p.A[s], (const float*)sm.p.B[s], wm, wn, tig, grp, c);
        __syncthreads();
    }

    stage_c(sm, c, wm, wn, tig, grp);
    __syncthreads();
    #pragma unroll
    for (int pass = 0; pass < 8; pass++) {
        int r = pass * 16 + (tid >> 4);
        int cq = (tid & 15) * 4;
        int gr = row0 + r;
        if (gr < M) {
            float z[4];
            z[0] = sm.C[r * CSTR + cq + 0]; z[1] = sm.C[r * CSTR + cq + 1];
            z[2] = sm.C[r * CSTR + cq + 2]; z[3] = sm.C[r * CSTR + cq + 3];
            float4 bv = *(const float4*)&gateB[col0 + cq];
            float4 p4 = *(const float4*)&prev[(size_t)gr * 256 + col0 + cq];
            float4 u4 = __ldcg((const float4*)&g_update[(size_t)gr * 256 + col0 + cq]);
            float4 o;
            float g0 = 1.f / (1.f + __expf(-(z[0] + bv.x)));
            float g1 = 1.f / (1.f + __expf(-(z[1] + bv.y)));
            float g2 = 1.f / (1.f + __expf(-(z[2] + bv.z)));
            float g3 = 1.f / (1.f + __expf(-(z[3] + bv.w)));
            o.x = g0 * p4.x + (1.f - g0) * u4.x;
            o.y = g1 * p4.y + (1.f - g1) * u4.y;
            o.z = g2 * p4.z + (1.f - g2) * u4.z;
            o.w = g3 * p4.w + (1.f - g3) * u4.w;
            *(float4*)&out[(size_t)gr * 256 + col0 + cq] = o;
        }
    }
}

// ---------------- launch ----------------
extern "C" void kernel_launch(void* const* d_in, const int* in_sizes, int n_in,
                              void* d_out, int out_size) {
    const float*   x     = (const float*)d_in[0];
    const void*    mask  = d_in[1];
    const int*     idx   = (const int*)d_in[2];
    const float*   prev  = (const float*)d_in[3];
    const float*   Wq    = (const float*)d_in[4];
    const float*   gateW = (const float*)d_in[5];
    const float*   gateB = (const float*)d_in[6];
    float*         out   = (float*)d_out;

    fused_gemm_fill_kernel<<<QBLOCKS + FILL_BLOCKS, 256>>>(prev, Wq, mask, idx);
    attn_kernel<<<NODES, 256>>>(x);

    // gate: programmatic dependent launch -> overlaps its prev-half with attn
    cudaLaunchConfig_t cfg = {};
    cfg.gridDim  = dim3(QGX, QGY);
    cfg.blockDim = dim3(256);
    cudaLaunchAttribute attrs[1];
    attrs[0].id = cudaLaunchAttributeProgrammaticStreamSerialization;
    attrs[0].val.programmaticStreamSerializationAllowed = 1;
    cfg.attrs = attrs;
    cfg.numAttrs = 1;
    cudaLaunchKernelEx(&cfg, gate_kernel, prev, gateW, gateB, out, NODES);
}

// round 13
// speedup vs baseline: 1.2221x; 1.2221x over previous
#include <cuda_runtime.h>
#include <cuda_bf16.h>
#include <cstdint>

#define NODES      10000
#define DIM        256
#define NTOT       262144          // 4096 * 64
#define CAP        128             // fixed per-node bucket capacity (mean E=13.1)

// ---------------- device scratch ----------------
// g_cursor: zero at module load; attn_kernel re-zeroes after use -> invariant
// "all cursors are 0 at kernel_launch entry" holds across graph replays.
__device__ float g_q[NODES * DIM];
__device__ float g_update[NODES * DIM];
__device__ int   g_cursor[NODES];
__device__ int   g_entries[NODES * CAP];

__device__ __forceinline__ void mma_tf32(float* c, const uint32_t* a, const uint32_t* b) {
    asm volatile(
        "mma.sync.aligned.m16n8k8.row.col.f32.tf32.tf32.f32 "
        "{%0,%1,%2,%3}, {%4,%5,%6,%7}, {%8,%9}, {%0,%1,%2,%3};"
        : "+f"(c[0]), "+f"(c[1]), "+f"(c[2]), "+f"(c[3])
        : "r"(a[0]), "r"(a[1]), "r"(a[2]), "r"(a[3]), "r"(b[0]), "r"(b[1]));
}

__device__ __forceinline__ void cp_async16p(void* dst, const void* src, bool pred) {
    uint32_t d = (uint32_t)__cvta_generic_to_shared(dst);
    int sz = pred ? 16 : 0;
    asm volatile("cp.async.cg.shared.global [%0], [%1], 16, %2;\n"
                 :: "r"(d), "l"(src), "r"(sz));
}
__device__ __forceinline__ void cp_async16(void* dst, const void* src) {
    uint32_t d = (uint32_t)__cvta_generic_to_shared(dst);
    asm volatile("cp.async.cg.shared.global [%0], [%1], 16;\n"
                 :: "r"(d), "l"(src));
}
#define CP_COMMIT() asm volatile("cp.async.commit_group;\n" ::)
#define CP_WAIT(n)  asm volatile("cp.async.wait_group %0;\n" :: "n"(n))

__device__ __forceinline__ bool read_mask(const void* m, int i, int mode) {
    if (mode == 1) return ((const uint8_t*)m)[i] != 0;
    if (mode == 2) return ((const float*)m)[i] != 0.0f;
    return ((const int*)m)[i] != 0;
}

// ---------------- GEMM geometry ----------------
#define GBM 128
#define GBN 64
#define QGX (256 / GBN)                          // 4
#define QGY ((NODES + GBM - 1) / GBM)            // 79
#define QBLOCKS (QGX * QGY)                      // 316
#define FILL_BLOCKS (NTOT / 4 / 256)             // 256
#define CSTR 65                                  // staged-C smem stride (floats)

union SmemU {
    struct { float4 A[2][1024]; float4 B[2][512]; } p;   // 48 KB
    float C[GBM * CSTR];                                  // 33.3 KB
    int   probe[2];
};

__device__ __forceinline__ int a_idx(int r, int k) {   // float index, A stage 128x32
    int ch = k >> 2;
    return r * 32 + ((ch ^ (r & 7)) << 2) + (k & 3);
}
__device__ __forceinline__ int b_idx(int k, int n) {   // float index, B stage 32x64
    int ch = n >> 2;
    return k * 64 + ((ch ^ ((k & 3) << 1)) << 2) + (n & 3);
}

__device__ __forceinline__ void load_a_tile(float4* sa, const float* __restrict__ Asrc,
                                            int row0, int k0, int M) {
    int tid = threadIdx.x;
    #pragma unroll
    for (int t = 0; t < 4; t++) {
        int cl = tid + t * 256;            // 0..1023
        int r = cl >> 3, ch = cl & 7;
        int gr = row0 + r;
        const float* src = Asrc + (size_t)gr * 256 + k0 + ch * 4;
        cp_async16p(&sa[r * 8 + (ch ^ (r & 7))], src, gr < M);
    }
}
__device__ __forceinline__ void load_b_tile(float4* sb, const float* __restrict__ Bsrc,
                                            int col0, int k0) {
    int tid = threadIdx.x;
    #pragma unroll
    for (int t = 0; t < 2; t++) {
        int cl = tid + t * 256;            // 0..511
        int k = cl >> 4, ch = cl & 15;
        const float* src = Bsrc + (size_t)(k0 + k) * 256 + col0 + ch * 4;
        cp_async16(&sb[k * 16 + (ch ^ ((k & 3) << 1))], src);
    }
}

__device__ __forceinline__ void mma_stage(const float* __restrict__ As,
                                          const float* __restrict__ Bs,
                                          int wm, int wn, int tig, int grp,
                                          float c[2][4][4]) {
    #pragma unroll
    for (int g = 0; g < 4; g++) {
        int k1 = g * 8 + tig;
        uint32_t a[2][4], b[4][2];
        #pragma unroll
        for (int mt = 0; mt < 2; mt++) {
            int r = wm * 32 + mt * 16 + grp;
            a[mt][0] = __float_as_uint(As[a_idx(r,     k1)]);
            a[mt][1] = __float_as_uint(As[a_idx(r + 8, k1)]);
            a[mt][2] = __float_as_uint(As[a_idx(r,     k1 + 4)]);
            a[mt][3] = __float_as_uint(As[a_idx(r + 8, k1 + 4)]);
        }
        #pragma unroll
        for (int nt = 0; nt < 4; nt++) {
            int cc = wn * 32 + nt * 8 + grp;
            b[nt][0] = __float_as_uint(Bs[b_idx(k1,     cc)]);
            b[nt][1] = __float_as_uint(Bs[b_idx(k1 + 4, cc)]);
        }
        #pragma unroll
        for (int mt = 0; mt < 2; mt++)
            #pragma unroll
            for (int nt = 0; nt < 4; nt++)
                mma_tf32(c[mt][nt], a[mt], b[nt]);
    }
}

// ---- stage accumulators into smem C (stride-65 avoids bank conflicts) ----
__device__ __forceinline__ void stage_c(SmemU& sm, float c[2][4][4],
                                        int wm, int wn, int tig, int grp) {
    #pragma unroll
    for (int mt = 0; mt < 2; mt++)
        #pragma unroll
        for (int i = 0; i < 2; i++) {
            int r = wm * 32 + mt * 16 + grp + i * 8;
            #pragma unroll
            for (int nt = 0; nt < 4; nt++)
                #pragma unroll
                for (int jj = 0; jj < 2; jj++) {
                    int cc = wn * 32 + nt * 8 + tig * 2 + jj;
                    sm.C[r * CSTR + cc] = c[mt][nt][i * 2 + jj];
                }
        }
}

// ---- q-GEMM body: cp.async double-buffered, K=256, coalesced staged store ----
__device__ void gemm_q_body(SmemU& sm, const float* __restrict__ A,
                            const float* __restrict__ B, int M, int bx, int by) {
    int tid = threadIdx.x;
    int wid = tid >> 5, lane = tid & 31;
    int tig = lane & 3, grp = lane >> 2;
    int wm = wid & 3, wn = wid >> 2;
    int row0 = by * GBM, col0 = bx * GBN;
    float c[2][4][4] = {};

    load_a_tile(sm.p.A[0], A, row0, 0, M);
    load_b_tile(sm.p.B[0], B, col0, 0);
    CP_COMMIT();
    const int T = 8;
    for (int t = 0; t < T; t++) {
        int s = t & 1;
        if (t + 1 < T) {
            load_a_tile(sm.p.A[s ^ 1], A, row0, (t + 1) * 32, M);
            load_b_tile(sm.p.B[s ^ 1], B, col0, (t + 1) * 32);
            CP_COMMIT();
            CP_WAIT(1);
        } else {
            CP_WAIT(0);
        }
        __syncthreads();
        mma_stage((const float*)sm.p.A[s], (const float*)sm.p.B[s], wm, wn, tig, grp, c);
        __syncthreads();
    }

    stage_c(sm, c, wm, wn, tig, grp);
    __syncthreads();
    #pragma unroll
    for (int pass = 0; pass < 8; pass++) {
        int r = pass * 16 + (tid >> 4);
        int cq = (tid & 15) * 4;
        int gr = row0 + r;
        if (gr < M) {
            float4 v;
            v.x = sm.C[r * CSTR + cq + 0]; v.y = sm.C[r * CSTR + cq + 1];
            v.z = sm.C[r * CSTR + cq + 2]; v.w = sm.C[r * CSTR + cq + 3];
            *(float4*)&g_q[(size_t)gr * 256 + col0 + cq] = v;
        }
    }
}

// ---- fill body: self-probing mask mode + bump-allocate into buckets ----
__device__ void fill_body(SmemU& sm, const void* __restrict__ mask,
                          const int* __restrict__ idx, int fb) {
    int tid = threadIdx.x;
    if (tid < 2) sm.probe[tid] = 0;
    __syncthreads();
    {
        const uint32_t* mw = (const uint32_t*)mask;
        int l1 = 0, l3 = 0;
        #pragma unroll
        for (int w = 0; w < 8; w++) {
            uint32_t v = mw[tid * 8 + w];
            if (v & 0x0000FF00u) l1++;
            if (v & 0xFF000000u) l3++;
        }
        if (l1) atomicAdd(&sm.probe[0], 1);
        if (l3) atomicAdd(&sm.probe[1], 1);
    }
    __syncthreads();
    int mode = sm.probe[0] ? 1 : (sm.probe[1] ? 2 : 0);

    int base = (fb * 256 + tid) * 4;
    if (base >= NTOT) return;
    int4 id4 = *(const int4*)&idx[base];
    int ids[4] = {id4.x, id4.y, id4.z, id4.w};
    #pragma unroll
    for (int j = 0; j < 4; j++) {
        if (read_mask(mask, base + j, mode)) {
            int n = ids[j];
            int p = atomicAdd(&g_cursor[n], 1);
            if (p < CAP) g_entries[n * CAP + p] = base + j;
        }
    }
}

// ---- fused: q-GEMM blocks + fill blocks in one wave ----
__global__ void fused_gemm_fill_kernel(const float* __restrict__ prev,
                                       const float* __restrict__ Wq,
                                       const void* __restrict__ mask,
                                       const int* __restrict__ idx) {
    __shared__ SmemU sm;
    int b = blockIdx.x;
    if (b < QBLOCKS) gemm_q_body(sm, prev, Wq, NODES, b % QGX, b / QGX);
    else             fill_body(sm, mask, idx, b - QBLOCKS);
}

// ---------------- per-node attention (exact fp32, 128 threads -> 16 CTA/SM) ----------------
#define ATHREADS 128
#define NWARPS_ATTN 4
__global__ void attn_kernel(const float* __restrict__ x) {   // [NTOT, 256]
    cudaTriggerProgrammaticLaunchCompletion();

    int node = blockIdx.x;
    int E   = min(g_cursor[node], CAP);
    int tid = threadIdx.x;             // 128; each thread owns cols tid, tid+128
    if (E == 0) {
        g_update[(size_t)node * DIM + tid] = 0.f;
        g_update[(size_t)node * DIM + tid + 128] = 0.f;
        return;
    }
    int lane = tid & 31, wid = tid >> 5;
    const int* gep = g_entries + node * CAP;

    __shared__ float s_sc[CAP];
    __shared__ int   s_en[CAP];
    for (int j = tid; j < E; j += ATHREADS) s_en[j] = gep[j];
    __syncthreads();
    if (tid == 0) g_cursor[node] = 0;   // reset for next launch (after all reads)

    // phase 1: scores, two entries per warp iteration (MLP=4)
    const float4* qr = (const float4*)(g_q + (size_t)node * DIM);
    float4 b0 = qr[lane * 2], b1 = qr[lane * 2 + 1];
    for (int j = wid * 2; j < E; j += 2 * NWARPS_ATTN) {
        int rA = s_en[j];
        bool has2 = (j + 1 < E);
        int rB = has2 ? s_en[j + 1] : rA;
        const float4* xA = (const float4*)(x + (size_t)rA * DIM);
        const float4* xB = (const float4*)(x + (size_t)rB * DIM);
        float4 a0 = xA[lane * 2], a1 = xA[lane * 2 + 1];
        float4 c0 = xB[lane * 2], c1 = xB[lane * 2 + 1];
        float sA = a0.x * b0.x + a0.y * b0.y + a0.z * b0.z + a0.w * b0.w
                 + a1.x * b1.x + a1.y * b1.y + a1.z * b1.z + a1.w * b1.w;
        float sB = c0.x * b0.x + c0.y * b0.y + c0.z * b0.z + c0.w * b0.w
                 + c1.x * b1.x + c1.y * b1.y + c1.z * b1.z + c1.w * b1.w;
        #pragma unroll
        for (int off = 16; off; off >>= 1) {
            sA += __shfl_down_sync(0xFFFFFFFFu, sA, off);
            sB += __shfl_down_sync(0xFFFFFFFFu, sB, off);
        }
        if (lane == 0) {
            s_sc[j] = sA * 0.0625f;
            if (has2) s_sc[j + 1] = sB * 0.0625f;
        }
    }
    __syncthreads();

    // phase 2: softmax by warp 0 alone
    if (wid == 0) {
        float mx = -1e30f;
        for (int j = lane; j < E; j += 32) mx = fmaxf(mx, s_sc[j]);
        #pragma unroll
        for (int off = 16; off; off >>= 1) mx = fmaxf(mx, __shfl_xor_sync(0xFFFFFFFFu, mx, off));
        float sm = 0.f;
        for (int j = lane; j < E; j += 32) sm += __expf(s_sc[j] - mx);
        #pragma unroll
        for (int off = 16; off; off >>= 1) sm += __shfl_xor_sync(0xFFFFFFFFu, sm, off);
        float inv = 1.f / fmaxf(sm, 1e-9f);
        for (int j = lane; j < E; j += 32) s_sc[j] = __expf(s_sc[j] - mx) * inv;
    }
    __syncthreads();

    // phase 3: weighted sum, two columns per thread, unrolled x4 for MLP
    float acc0 = 0.f, acc1 = 0.f;
    int j = 0;
    for (; j + 4 <= E; j += 4) {
        int r0 = s_en[j], r1 = s_en[j + 1], r2 = s_en[j + 2], r3 = s_en[j + 3];
        float w0 = s_sc[j], w1 = s_sc[j + 1], w2 = s_sc[j + 2], w3 = s_sc[j + 3];
        const float* p0 = x + (size_t)r0 * DIM;
        const float* p1 = x + (size_t)r1 * DIM;
        const float* p2 = x + (size_t)r2 * DIM;
        const float* p3 = x + (size_t)r3 * DIM;
        acc0 += w0 * p0[tid]       + w1 * p1[tid]       + w2 * p2[tid]       + w3 * p3[tid];
        acc1 += w0 * p0[tid + 128] + w1 * p1[tid + 128] + w2 * p2[tid + 128] + w3 * p3[tid + 128];
    }
    for (; j < E; j++) {
        const float* p = x + (size_t)s_en[j] * DIM;
        float w = s_sc[j];
        acc0 += w * p[tid];
        acc1 += w * p[tid + 128];
    }
    g_update[(size_t)node * DIM + tid]       = acc0;
    g_update[(size_t)node * DIM + tid + 128] = acc1;
}

// ---------------- gate: PDL-overlapped tf32 GEMM (K=512) ----------------
__global__ void gate_kernel(const float* __restrict__ prev,
                            const float* __restrict__ gateW,
                            const float* __restrict__ gateB,
                            float* __restrict__ out, int M) {
    __shared__ SmemU sm;
    int tid = threadIdx.x;
    int wid = tid >> 5, lane = tid & 31;
    int tig = lane & 3, grp = lane >> 2;
    int wm = wid & 3, wn = wid >> 2;
    int row0 = blockIdx.y * GBM, col0 = blockIdx.x * GBN;
    float c[2][4][4] = {};

    load_a_tile(sm.p.A[0], prev, row0, 0, M);
    load_b_tile(sm.p.B[0], gateW, col0, 0);
    CP_COMMIT();
    const int T = 16;                    // K = 512
    for (int t = 0; t < T; t++) {
        int s = t & 1;
        if (t + 1 < T) {
            int kt = t + 1;
            if (kt == 8) cudaGridDependencySynchronize();   // wait for attn grid
            const float* Asrc = (kt < 8) ? prev : g_update;
            load_a_tile(sm.p.A[s ^ 1], Asrc, row0, (kt * 32) & 255, M);
            load_b_tile(sm.p.B[s ^ 1], gateW, col0, kt * 32);
            CP_COMMIT();
            CP_WAIT(1);
        } else {
            CP_WAIT(0);
        }
        __syncthreads();
        mma_stage((const float*)sm.p.A[s], (const float*)sm.p.B[s], wm, wn, tig, grp, c);
        __syncthreads();
    }

    stage_c(sm, c, wm, wn, tig, grp);
    __syncthreads();
    #pragma unroll
    for (int pass = 0; pass < 8; pass++) {
        int r = pass * 16 + (tid >> 4);
        int cq = (tid & 15) * 4;
        int gr = row0 + r;
        if (gr < M) {
            float z[4];
            z[0] = sm.C[r * CSTR + cq + 0]; z[1] = sm.C[r * CSTR + cq + 1];
            z[2] = sm.C[r * CSTR + cq + 2]; z[3] = sm.C[r * CSTR + cq + 3];
            float4 bv = *(const float4*)&gateB[col0 + cq];
            float4 p4 = *(const float4*)&prev[(size_t)gr * 256 + col0 + cq];
            float4 u4 = __ldcg((const float4*)&g_update[(size_t)gr * 256 + col0 + cq]);
            float4 o;
            float g0 = 1.f / (1.f + __expf(-(z[0] + bv.x)));
            float g1 = 1.f / (1.f + __expf(-(z[1] + bv.y)));
            float g2 = 1.f / (1.f + __expf(-(z[2] + bv.z)));
            float g3 = 1.f / (1.f + __expf(-(z[3] + bv.w)));
            o.x = g0 * p4.x + (1.f - g0) * u4.x;
            o.y = g1 * p4.y + (1.f - g1) * u4.y;
            o.z = g2 * p4.z + (1.f - g2) * u4.z;
            o.w = g3 * p4.w + (1.f - g3) * u4.w;
            *(float4*)&out[(size_t)gr * 256 + col0 + cq] = o;
        }
    }
}

// ---------------- launch ----------------
extern "C" void kernel_launch(void* const* d_in, const int* in_sizes, int n_in,
                              void* d_out, int out_size) {
    const float*   x     = (const float*)d_in[0];
    const void*    mask  = d_in[1];
    const int*     idx   = (const int*)d_in[2];
    const float*   prev  = (const float*)d_in[3];
    const float*   Wq    = (const float*)d_in[4];
    const float*   gateW = (const float*)d_in[5];
    const float*   gateB = (const float*)d_in[6];
    float*         out   = (float*)d_out;

    fused_gemm_fill_kernel<<<QBLOCKS + FILL_BLOCKS, 256>>>(prev, Wq, mask, idx);
    attn_kernel<<<NODES, ATHREADS>>>(x);

    // gate: programmatic dependent launch -> overlaps its prev-half with attn
    cudaLaunchConfig_t cfg = {};
    cfg.gridDim  = dim3(QGX, QGY);
    cfg.blockDim = dim3(256);
    cudaLaunchAttribute attrs[1];
    attrs[0].id = cudaLaunchAttributeProgrammaticStreamSerialization;
    attrs[0].val.programmaticStreamSerializationAllowed = 1;
    cfg.attrs = attrs;
    cfg.numAttrs = 1;
    cudaLaunchKernelEx(&cfg, gate_kernel, prev, gateW, gateB, out, NODES);
}

// round 14
// speedup vs baseline: 1.2935x; 1.0585x over previous
#include <cuda_runtime.h>
#include <cuda_bf16.h>
#include <cstdint>

#define NODES      10000
#define DIM        256
#define NTOT       262144          // 4096 * 64
#define CAP        128             // fixed per-node bucket capacity (mean E=13.1)

// ---------------- device scratch ----------------
// g_cursor: zero at module load; attn_kernel re-zeroes after use -> invariant
// "all cursors are 0 at kernel_launch entry" holds across graph replays.
__device__ float g_q[NODES * DIM];
__device__ float g_update[NODES * DIM];
__device__ int   g_cursor[NODES];
__device__ int   g_entries[NODES * CAP];

__device__ __forceinline__ void mma_tf32(float* c, const uint32_t* a, const uint32_t* b) {
    asm volatile(
        "mma.sync.aligned.m16n8k8.row.col.f32.tf32.tf32.f32 "
        "{%0,%1,%2,%3}, {%4,%5,%6,%7}, {%8,%9}, {%0,%1,%2,%3};"
        : "+f"(c[0]), "+f"(c[1]), "+f"(c[2]), "+f"(c[3])
        : "r"(a[0]), "r"(a[1]), "r"(a[2]), "r"(a[3]), "r"(b[0]), "r"(b[1]));
}

__device__ __forceinline__ void cp_async16p(void* dst, const void* src, bool pred) {
    uint32_t d = (uint32_t)__cvta_generic_to_shared(dst);
    int sz = pred ? 16 : 0;
    asm volatile("cp.async.cg.shared.global [%0], [%1], 16, %2;\n"
                 :: "r"(d), "l"(src), "r"(sz));
}
__device__ __forceinline__ void cp_async16(void* dst, const void* src) {
    uint32_t d = (uint32_t)__cvta_generic_to_shared(dst);
    asm volatile("cp.async.cg.shared.global [%0], [%1], 16;\n"
                 :: "r"(d), "l"(src));
}
#define CP_COMMIT() asm volatile("cp.async.commit_group;\n" ::)
#define CP_WAIT(n)  asm volatile("cp.async.wait_group %0;\n" :: "n"(n))

__device__ __forceinline__ bool read_mask(const void* m, int i, int mode) {
    if (mode == 1) return ((const uint8_t*)m)[i] != 0;
    if (mode == 2) return ((const float*)m)[i] != 0.0f;
    return ((const int*)m)[i] != 0;
}

// ---------------- GEMM geometry ----------------
#define GBM 128
#define GBN 64
#define QGX (256 / GBN)                          // 4
#define QGY ((NODES + GBM - 1) / GBM)            // 79
#define QBLOCKS (QGX * QGY)                      // 316
#define FILL_BLOCKS (NTOT / 4 / 256)             // 256
#define CSTR 65                                  // staged-C smem stride (floats)

union SmemU {
    struct { float4 A[2][1024]; float4 B[2][512]; } p;   // 48 KB
    float C[GBM * CSTR];                                  // 33.3 KB
    int   probe[2];
};

__device__ __forceinline__ int a_idx(int r, int k) {   // float index, A stage 128x32
    int ch = k >> 2;
    return r * 32 + ((ch ^ (r & 7)) << 2) + (k & 3);
}
__device__ __forceinline__ int b_idx(int k, int n) {   // float index, B stage 32x64
    int ch = n >> 2;
    return k * 64 + ((ch ^ ((k & 3) << 1)) << 2) + (n & 3);
}

__device__ __forceinline__ void load_a_tile(float4* sa, const float* __restrict__ Asrc,
                                            int row0, int k0, int M) {
    int tid = threadIdx.x;
    #pragma unroll
    for (int t = 0; t < 4; t++) {
        int cl = tid + t * 256;            // 0..1023
        int r = cl >> 3, ch = cl & 7;
        int gr = row0 + r;
        const float* src = Asrc + (size_t)gr * 256 + k0 + ch * 4;
        cp_async16p(&sa[r * 8 + (ch ^ (r & 7))], src, gr < M);
    }
}
__device__ __forceinline__ void load_b_tile(float4* sb, const float* __restrict__ Bsrc,
                                            int col0, int k0) {
    int tid = threadIdx.x;
    #pragma unroll
    for (int t = 0; t < 2; t++) {
        int cl = tid + t * 256;            // 0..511
        int k = cl >> 4, ch = cl & 15;
        const float* src = Bsrc + (size_t)(k0 + k) * 256 + col0 + ch * 4;
        cp_async16(&sb[k * 16 + (ch ^ ((k & 3) << 1))], src);
    }
}

__device__ __forceinline__ void mma_stage(const float* __restrict__ As,
                                          const float* __restrict__ Bs,
                                          int wm, int wn, int tig, int grp,
                                          float c[2][4][4]) {
    #pragma unroll
    for (int g = 0; g < 4; g++) {
        int k1 = g * 8 + tig;
        uint32_t a[2][4], b[4][2];
        #pragma unroll
        for (int mt = 0; mt < 2; mt++) {
            int r = wm * 32 + mt * 16 + grp;
            a[mt][0] = __float_as_uint(As[a_idx(r,     k1)]);
            a[mt][1] = __float_as_uint(As[a_idx(r + 8, k1)]);
            a[mt][2] = __float_as_uint(As[a_idx(r,     k1 + 4)]);
            a[mt][3] = __float_as_uint(As[a_idx(r + 8, k1 + 4)]);
        }
        #pragma unroll
        for (int nt = 0; nt < 4; nt++) {
            int cc = wn * 32 + nt * 8 + grp;
            b[nt][0] = __float_as_uint(Bs[b_idx(k1,     cc)]);
            b[nt][1] = __float_as_uint(Bs[b_idx(k1 + 4, cc)]);
        }
        #pragma unroll
        for (int mt = 0; mt < 2; mt++)
            #pragma unroll
            for (int nt = 0; nt < 4; nt++)
                mma_tf32(c[mt][nt], a[mt], b[nt]);
    }
}

// ---- stage accumulators into smem C (stride-65 avoids bank conflicts) ----
__device__ __forceinline__ void stage_c(SmemU& sm, float c[2][4][4],
                                        int wm, int wn, int tig, int grp) {
    #pragma unroll
    for (int mt = 0; mt < 2; mt++)
        #pragma unroll
        for (int i = 0; i < 2; i++) {
            int r = wm * 32 + mt * 16 + grp + i * 8;
            #pragma unroll
            for (int nt = 0; nt < 4; nt++)
                #pragma unroll
                for (int jj = 0; jj < 2; jj++) {
                    int cc = wn * 32 + nt * 8 + tig * 2 + jj;
                    sm.C[r * CSTR + cc] = c[mt][nt][i * 2 + jj];
                }
        }
}

// ---- q-GEMM body: cp.async double-buffered, K=256, coalesced staged store ----
__device__ void gemm_q_body(SmemU& sm, const float* __restrict__ A,
                            const float* __restrict__ B, int M, int bx, int by) {
    int tid = threadIdx.x;
    int wid = tid >> 5, lane = tid & 31;
    int tig = lane & 3, grp = lane >> 2;
    int wm = wid & 3, wn = wid >> 2;
    int row0 = by * GBM, col0 = bx * GBN;
    float c[2][4][4] = {};

    load_a_tile(sm.p.A[0], A, row0, 0, M);
    load_b_tile(sm.p.B[0], B, col0, 0);
    CP_COMMIT();
    const int T = 8;
    for (int t = 0; t < T; t++) {
        int s = t & 1;
        if (t + 1 < T) {
            load_a_tile(sm.p.A[s ^ 1], A, row0, (t + 1) * 32, M);
            load_b_tile(sm.p.B[s ^ 1], B, col0, (t + 1) * 32);
            CP_COMMIT();
            CP_WAIT(1);
        } else {
            CP_WAIT(0);
        }
        __syncthreads();
        mma_stage((const float*)sm.p.A[s], (const float*)sm.p.B[s], wm, wn, tig, grp, c);
        __syncthreads();
    }

    stage_c(sm, c, wm, wn, tig, grp);
    __syncthreads();
    #pragma unroll
    for (int pass = 0; pass < 8; pass++) {
        int r = pass * 16 + (tid >> 4);
        int cq = (tid & 15) * 4;
        int gr = row0 + r;
        if (gr < M) {
            float4 v;
            v.x = sm.C[r * CSTR + cq + 0]; v.y = sm.C[r * CSTR + cq + 1];
            v.z = sm.C[r * CSTR + cq + 2]; v.w = sm.C[r * CSTR + cq + 3];
            *(float4*)&g_q[(size_t)gr * 256 + col0 + cq] = v;
        }
    }
}

// ---- fill body: self-probing mask mode + bump-allocate into buckets ----
__device__ void fill_body(SmemU& sm, const void* __restrict__ mask,
                          const int* __restrict__ idx, int fb) {
    int tid = threadIdx.x;
    if (tid < 2) sm.probe[tid] = 0;
    __syncthreads();
    {
        const uint32_t* mw = (const uint32_t*)mask;
        int l1 = 0, l3 = 0;
        #pragma unroll
        for (int w = 0; w < 8; w++) {
            uint32_t v = mw[tid * 8 + w];
            if (v & 0x0000FF00u) l1++;
            if (v & 0xFF000000u) l3++;
        }
        if (l1) atomicAdd(&sm.probe[0], 1);
        if (l3) atomicAdd(&sm.probe[1], 1);
    }
    __syncthreads();
    int mode = sm.probe[0] ? 1 : (sm.probe[1] ? 2 : 0);

    int base = (fb * 256 + tid) * 4;
    if (base >= NTOT) return;
    int4 id4 = *(const int4*)&idx[base];
    int ids[4] = {id4.x, id4.y, id4.z, id4.w};
    #pragma unroll
    for (int j = 0; j < 4; j++) {
        if (read_mask(mask, base + j, mode)) {
            int n = ids[j];
            int p = atomicAdd(&g_cursor[n], 1);
            if (p < CAP) g_entries[n * CAP + p] = base + j;
        }
    }
}

// ---- fused: q-GEMM blocks + fill blocks in one wave ----
__global__ void fused_gemm_fill_kernel(const float* __restrict__ prev,
                                       const float* __restrict__ Wq,
                                       const void* __restrict__ mask,
                                       const int* __restrict__ idx) {
    __shared__ SmemU sm;
    int b = blockIdx.x;
    if (b < QBLOCKS) gemm_q_body(sm, prev, Wq, NODES, b % QGX, b / QGX);
    else             fill_body(sm, mask, idx, b - QBLOCKS);
}

// ---------------- per-node attention: one-pass online softmax (flash-style) ----------------
// Each warp streams its entries once, keeping running (m, sum, acc) with rescaling.
// 4-warp merge at the end. x is read exactly ONCE (phase-3 re-read eliminated).
#define ATHREADS 128
__global__ void attn_kernel(const float* __restrict__ x) {   // [NTOT, 256]
    cudaGridDependencySynchronize();                  // fused grid must be complete
    cudaTriggerProgrammaticLaunchCompletion();        // let gate front-run its prev-half

    int node = blockIdx.x;
    int E   = min(g_cursor[node], CAP);
    int tid = threadIdx.x;             // 128; lane owns cols [lane*8, lane*8+8) per warp
    int lane = tid & 31, wid = tid >> 5;
    if (E == 0) {
        g_update[(size_t)node * DIM + tid] = 0.f;
        g_update[(size_t)node * DIM + tid + 128] = 0.f;
        return;
    }
    const int* gep = g_entries + node * CAP;

    __shared__ int   s_en[CAP];
    __shared__ float s_m[4], s_s[4];
    __shared__ float s_wacc[4][DIM];
    for (int j = tid; j < E; j += ATHREADS) s_en[j] = gep[j];
    __syncthreads();
    if (tid == 0) g_cursor[node] = 0;   // reset for next launch (after all reads)

    const float4* qr = (const float4*)(g_q + (size_t)node * DIM);
    float4 b0 = qr[lane * 2], b1 = qr[lane * 2 + 1];

    float m = -1e30f, ssum = 0.f;
    float4 acc0 = make_float4(0.f, 0.f, 0.f, 0.f);
    float4 acc1 = make_float4(0.f, 0.f, 0.f, 0.f);

    for (int j = wid * 2; j < E; j += 8) {
        int rA = s_en[j];
        bool has2 = (j + 1 < E);
        int rB = has2 ? s_en[j + 1] : rA;
        const float4* xA = (const float4*)(x + (size_t)rA * DIM);
        const float4* xB = (const float4*)(x + (size_t)rB * DIM);
        float4 a0 = xA[lane * 2], a1 = xA[lane * 2 + 1];
        float4 c0 = xB[lane * 2], c1 = xB[lane * 2 + 1];
        float sA = a0.x * b0.x + a0.y * b0.y + a0.z * b0.z + a0.w * b0.w
                 + a1.x * b1.x + a1.y * b1.y + a1.z * b1.z + a1.w * b1.w;
        float sB = c0.x * b0.x + c0.y * b0.y + c0.z * b0.z + c0.w * b0.w
                 + c1.x * b1.x + c1.y * b1.y + c1.z * b1.z + c1.w * b1.w;
        #pragma unroll
        for (int off = 16; off; off >>= 1) {
            sA += __shfl_xor_sync(0xFFFFFFFFu, sA, off);
            sB += __shfl_xor_sync(0xFFFFFFFFu, sB, off);
        }
        sA *= 0.0625f;
        sB = has2 ? sB * 0.0625f : -1e30f;
        float mn = fmaxf(m, fmaxf(sA, sB));
        float r  = __expf(m - mn);              // 0 on first iteration (m = -1e30)
        float eA = __expf(sA - mn);
        float eB = has2 ? __expf(sB - mn) : 0.f;
        ssum = ssum * r + eA + eB;
        acc0.x = acc0.x * r + eA * a0.x + eB * c0.x;
        acc0.y = acc0.y * r + eA * a0.y + eB * c0.y;
        acc0.z = acc0.z * r + eA * a0.z + eB * c0.z;
        acc0.w = acc0.w * r + eA * a0.w + eB * c0.w;
        acc1.x = acc1.x * r + eA * a1.x + eB * c1.x;
        acc1.y = acc1.y * r + eA * a1.y + eB * c1.y;
        acc1.z = acc1.z * r + eA * a1.z + eB * c1.z;
        acc1.w = acc1.w * r + eA * a1.w + eB * c1.w;
        m = mn;
    }

    // cross-warp merge
    float4* wa = (float4*)&s_wacc[wid][lane * 8];
    wa[0] = acc0; wa[1] = acc1;
    if (lane == 0) { s_m[wid] = m; s_s[wid] = ssum; }
    __syncthreads();

    float M4 = fmaxf(fmaxf(s_m[0], s_m[1]), fmaxf(s_m[2], s_m[3]));
    float f0 = __expf(s_m[0] - M4), f1 = __expf(s_m[1] - M4);
    float f2 = __expf(s_m[2] - M4), f3 = __expf(s_m[3] - M4);
    float total = s_s[0] * f0 + s_s[1] * f1 + s_s[2] * f2 + s_s[3] * f3;
    float inv = 1.f / fmaxf(total, 1e-9f);
    #pragma unroll
    for (int h = 0; h < 2; h++) {
        int c = tid + h * 128;
        float v = s_wacc[0][c] * f0 + s_wacc[1][c] * f1
                + s_wacc[2][c] * f2 + s_wacc[3][c] * f3;
        g_update[(size_t)node * DIM + c] = v * inv;
    }
}

// ---------------- gate: PDL-overlapped tf32 GEMM (K=512) ----------------
__global__ void gate_kernel(const float* __restrict__ prev,
                            const float* __restrict__ gateW,
                            const float* __restrict__ gateB,
                            float* __restrict__ out, int M) {
    __shared__ SmemU sm;
    int tid = threadIdx.x;
    int wid = tid >> 5, lane = tid & 31;
    int tig = lane & 3, grp = lane >> 2;
    int wm = wid & 3, wn = wid >> 2;
    int row0 = blockIdx.y * GBM, col0 = blockIdx.x * GBN;
    float c[2][4][4] = {};

    load_a_tile(sm.p.A[0], prev, row0, 0, M);
    load_b_tile(sm.p.B[0], gateW, col0, 0);
    CP_COMMIT();
    const int T = 16;                    // K = 512
    for (int t = 0; t < T; t++) {
        int s = t & 1;
        if (t + 1 < T) {
            int kt = t + 1;
            if (kt == 8) cudaGridDependencySynchronize();   // wait for attn grid
            const float* Asrc = (kt < 8) ? prev : g_update;
            load_a_tile(sm.p.A[s ^ 1], Asrc, row0, (kt * 32) & 255, M);
            load_b_tile(sm.p.B[s ^ 1], gateW, col0, kt * 32);
            CP_COMMIT();
            CP_WAIT(1);
        } else {
            CP_WAIT(0);
        }
        __syncthreads();
        mma_stage((const float*)sm.p.A[s], (const float*)sm.p.B[s], wm, wn, tig, grp, c);
        __syncthreads();
    }

    stage_c(sm, c, wm, wn, tig, grp);
    __syncthreads();
    #pragma unroll
    for (int pass = 0; pass < 8; pass++) {
        int r = pass * 16 + (tid >> 4);
        int cq = (tid & 15) * 4;
        int gr = row0 + r;
        if (gr < M) {
            float z[4];
            z[0] = sm.C[r * CSTR + cq + 0]; z[1] = sm.C[r * CSTR + cq + 1];
            z[2] = sm.C[r * CSTR + cq + 2]; z[3] = sm.C[r * CSTR + cq + 3];
            float4 bv = *(const float4*)&gateB[col0 + cq];
            float4 p4 = *(const float4*)&prev[(size_t)gr * 256 + col0 + cq];
            float4 u4 = __ldcg((const float4*)&g_update[(size_t)gr * 256 + col0 + cq]);
            float4 o;
            float g0 = 1.f / (1.f + __expf(-(z[0] + bv.x)));
            float g1 = 1.f / (1.f + __expf(-(z[1] + bv.y)));
            float g2 = 1.f / (1.f + __expf(-(z[2] + bv.z)));
            float g3 = 1.f / (1.f + __expf(-(z[3] + bv.w)));
            o.x = g0 * p4.x + (1.f - g0) * u4.x;
            o.y = g1 * p4.y + (1.f - g1) * u4.y;
            o.z = g2 * p4.z + (1.f - g2) * u4.z;
            o.w = g3 * p4.w + (1.f - g3) * u4.w;
            *(float4*)&out[(size_t)gr * 256 + col0 + cq] = o;
        }
    }
}

// ---------------- launch ----------------
extern "C" void kernel_launch(void* const* d_in, const int* in_sizes, int n_in,
                              void* d_out, int out_size) {
    const float*   x     = (const float*)d_in[0];
    const void*    mask  = d_in[1];
    const int*     idx   = (const int*)d_in[2];
    const float*   prev  = (const float*)d_in[3];
    const float*   Wq    = (const float*)d_in[4];
    const float*   gateW = (const float*)d_in[5];
    const float*   gateB = (const float*)d_in[6];
    float*         out   = (float*)d_out;

    fused_gemm_fill_kernel<<<QBLOCKS + FILL_BLOCKS, 256>>>(prev, Wq, mask, idx);

    cudaLaunchAttribute pdl[1];
    pdl[0].id = cudaLaunchAttributeProgrammaticStreamSerialization;
    pdl[0].val.programmaticStreamSerializationAllowed = 1;

    // attn: PDL chains off fused (gridDepSync inside before cursor reads)
    cudaLaunchConfig_t acfg = {};
    acfg.gridDim  = dim3(NODES);
    acfg.blockDim = dim3(ATHREADS);
    acfg.attrs = pdl;
    acfg.numAttrs = 1;
    cudaLaunchKernelEx(&acfg, attn_kernel, x);

    // gate: PDL chains off attn -> overlaps its prev-half with attn
    cudaLaunchConfig_t gcfg = {};
    gcfg.gridDim  = dim3(QGX, QGY);
    gcfg.blockDim = dim3(256);
    gcfg.attrs = pdl;
    gcfg.numAttrs = 1;
    cudaLaunchKernelEx(&gcfg, gate_kernel, prev, gateW, gateB, out, NODES);
}